// round 1
// baseline (speedup 1.0000x reference)
#include <cuda_runtime.h>
#include <math.h>

#define T_STEPS 200
#define B 256
#define XD 128
#define H 512
#define ZD 64
#define OD 256
#define G3 1536
#define NBLK 148
#define NTHR 256

// ---------------- scratch (device globals: sanctioned scratch, no allocs) ----------
__device__ float g_phi[(size_t)T_STEPS * B * H];   // phi_x(x) for all t  (~100MB)
__device__ float g_tmp[(size_t)T_STEPS * B * H];   // phi_x hidden        (~100MB)
__device__ float g_h [B * H];
__device__ float g_pr[B * H];
__device__ float g_e1[B * H];
__device__ float g_e2[B * H];
__device__ float g_pz[B * H];
__device__ float g_d1[B * H];
__device__ float g_d2[B * H];
__device__ float g_gx[B * G3];
__device__ float g_gh[B * G3];

// ---------------- grid barrier (sense-reversing, replay-safe) ----------------------
__device__ unsigned int g_bar = 0;
__device__ volatile unsigned int g_sense = 0;

__device__ __forceinline__ void gsync(unsigned* gen, bool last) {
    __syncthreads();
    if (threadIdx.x == 0) {
        __threadfence();
        unsigned g = *gen;
        if (atomicAdd(&g_bar, 1u) == (unsigned)(NBLK - 1)) {
            g_bar = 0u;
            __threadfence();
            g_sense = last ? 0u : (g + 1u);   // reset to 0 on final barrier => replay-safe
        } else {
            while (g_sense == g) { __nanosleep(64); }
            __threadfence();
        }
    }
    __syncthreads();
    (*gen)++;
}

// ---------------- activation ----------------
__device__ __forceinline__ float actf(float v, int act) {
    if (act == 1) return fmaxf(v, 0.f);
    if (act == 2) return fmaxf(v, 0.f) + log1pf(expf(-fabsf(v)));  // stable softplus
    return v;
}

// ---------------- generic 64x64 output-tile GEMM (fp32 FFMA) ----------------
// C[row0:row0+64, col0:col0+64] = act( A @ W + bias )
// amode 0: A = A0 (rows x k0)
// amode 1: A = concat(A0 [rows x k0], A1 [rows x k1]) along k
// amode 2: A[r,k] = A0[r*k0+k]*A1[r*k0+k] + A2[r*k0+k]   (z = eps*es + em), K = k0
__device__ __noinline__ void gemm64(
    float* As, float* Bs, int amode,
    const float* __restrict__ A0, const float* __restrict__ A1, const float* __restrict__ A2,
    int k0, int k1,
    const float* __restrict__ W, const float* __restrict__ bias, int N,
    float* __restrict__ C, int ldc, int row0, int col0, int act)
{
    const int tid = threadIdx.x;
    const int tx = tid & 15, ty = tid >> 4;
    float acc[4][4];
#pragma unroll
    for (int i = 0; i < 4; i++)
#pragma unroll
        for (int j = 0; j < 4; j++) acc[i][j] = 0.f;

    const int K = k0 + k1;
    for (int kb = 0; kb < K; kb += 32) {
        // load A tile: 64 rows x 32 k, coalesced along k.  As layout [m][kk], stride 33
#pragma unroll
        for (int l = 0; l < 8; l++) {
            int idx = tid + l * NTHR;
            int m = idx >> 5, kk = idx & 31;
            int k = kb + kk, r = row0 + m;
            float a;
            if (amode == 2) {
                int o = r * k0 + k;
                a = A0[o] * A1[o] + A2[o];
            } else if (k < k0) {
                a = A0[r * k0 + k];
            } else {
                a = A1[r * k1 + (k - k0)];
            }
            As[m * 33 + kk] = a;
        }
        // load W tile: 32 k x 64 n, coalesced along n.  Bs layout [kk][n]
#pragma unroll
        for (int l = 0; l < 8; l++) {
            int idx = tid + l * NTHR;
            int kk = idx >> 6, n = idx & 63;
            Bs[kk * 64 + n] = W[(kb + kk) * N + col0 + n];
        }
        __syncthreads();
#pragma unroll
        for (int kk = 0; kk < 32; kk++) {
            float a[4], b[4];
#pragma unroll
            for (int i = 0; i < 4; i++) a[i] = As[(ty + 16 * i) * 33 + kk];
#pragma unroll
            for (int j = 0; j < 4; j++) b[j] = Bs[kk * 64 + tx + 16 * j];
#pragma unroll
            for (int i = 0; i < 4; i++)
#pragma unroll
                for (int j = 0; j < 4; j++) acc[i][j] = fmaf(a[i], b[j], acc[i][j]);
        }
        __syncthreads();
    }
#pragma unroll
    for (int j = 0; j < 4; j++) {
        int c = col0 + tx + 16 * j;
        float bv = bias[c];
#pragma unroll
        for (int i = 0; i < 4; i++) {
            float v = acc[i][j] + bv;
            C[(row0 + ty + 16 * i) * ldc + c] = actf(v, act);
        }
    }
}

// ---------------- kernel params ----------------
struct Params {
    const float *x, *eps;
    const float *pxw1, *pxb1, *pxw2, *pxb2;
    const float *pzw, *pzb;
    const float *ew1, *eb1, *ew2, *eb2, *emw, *emb, *esw, *esb;
    const float *prw, *prb, *pmw, *pmb, *psw, *psb;
    const float *dw1, *db1, *dw2, *db2, *dlw, *dlb;
    const float *gwih, *gbih, *gwhh, *gbhh;
    float *oz, *olog, *oem, *oes, *opm, *ops, *okld;
};

__global__ void __launch_bounds__(NTHR) vrnn_kernel(Params p) {
    __shared__ float As[64 * 33];
    __shared__ float Bs[32 * 64];
    unsigned gen = 0;

    // zero h0 (replay-safe: done every launch)
    for (int e = blockIdx.x * NTHR + threadIdx.x; e < B * H; e += NBLK * NTHR) g_h[e] = 0.f;

    // ---- phi_x over all timesteps ----
    // tmp = relu(x @ w1 + b1): [T*B, 512], K=128
    for (int idx = blockIdx.x; idx < (T_STEPS * B / 64) * 8; idx += NBLK) {
        int tm = idx >> 3, tn = idx & 7;
        gemm64(As, Bs, 0, p.x, 0, 0, XD, 0, p.pxw1, p.pxb1, H, g_tmp, H, tm * 64, tn * 64, 1);
    }
    gsync(&gen, false);
    // phi = relu(tmp @ w2 + b2): K=512
    for (int idx = blockIdx.x; idx < (T_STEPS * B / 64) * 8; idx += NBLK) {
        int tm = idx >> 3, tn = idx & 7;
        gemm64(As, Bs, 0, g_tmp, 0, 0, H, 0, p.pxw2, p.pxb2, H, g_phi, H, tm * 64, tn * 64, 1);
    }
    gsync(&gen, false);

    for (int t = 0; t < T_STEPS; t++) {
        const float* px = g_phi + (size_t)t * B * H;

        // ---- Phase A: pr(32) | gh(96) | e1(32) | logits[t-1](16) ----
        {
            int nt = 160 + (t > 0 ? 16 : 0);
            for (int idx = blockIdx.x; idx < nt; idx += NBLK) {
                if (idx < 32) {
                    int tm = idx >> 3, tn = idx & 7;
                    gemm64(As, Bs, 0, g_h, 0, 0, H, 0, p.prw, p.prb, H, g_pr, H, tm * 64, tn * 64, 1);
                } else if (idx < 128) {
                    int i2 = idx - 32; int tm = i2 / 24, tn = i2 % 24;
                    gemm64(As, Bs, 0, g_h, 0, 0, H, 0, p.gwhh, p.gbhh, G3, g_gh, G3, tm * 64, tn * 64, 0);
                } else if (idx < 160) {
                    int i2 = idx - 128; int tm = i2 >> 3, tn = i2 & 7;
                    gemm64(As, Bs, 1, px, g_h, 0, H, H, p.ew1, p.eb1, H, g_e1, H, tm * 64, tn * 64, 1);
                } else {
                    int i2 = idx - 160; int tm = i2 >> 2, tn = i2 & 3;
                    gemm64(As, Bs, 0, g_d2, 0, 0, H, 0, p.dlw, p.dlb, OD,
                           p.olog + (size_t)(t - 1) * B * OD, OD, tm * 64, tn * 64, 0);
                }
            }
            gsync(&gen, false);
        }
        // ---- Phase B: e2(32) | pm(4) | ps(4) ----
        {
            for (int idx = blockIdx.x; idx < 40; idx += NBLK) {
                if (idx < 32) {
                    int tm = idx >> 3, tn = idx & 7;
                    gemm64(As, Bs, 0, g_e1, 0, 0, H, 0, p.ew2, p.eb2, H, g_e2, H, tm * 64, tn * 64, 1);
                } else if (idx < 36) {
                    int tm = idx - 32;
                    gemm64(As, Bs, 0, g_pr, 0, 0, H, 0, p.pmw, p.pmb, ZD,
                           p.opm + (size_t)t * B * ZD, ZD, tm * 64, 0, 0);
                } else {
                    int tm = idx - 36;
                    gemm64(As, Bs, 0, g_pr, 0, 0, H, 0, p.psw, p.psb, ZD,
                           p.ops + (size_t)t * B * ZD, ZD, tm * 64, 0, 2);
                }
            }
            gsync(&gen, false);
        }
        // ---- Phase C: em(4) | es(4) ----
        {
            for (int idx = blockIdx.x; idx < 8; idx += NBLK) {
                if (idx < 4) {
                    gemm64(As, Bs, 0, g_e2, 0, 0, H, 0, p.emw, p.emb, ZD,
                           p.oem + (size_t)t * B * ZD, ZD, idx * 64, 0, 0);
                } else {
                    gemm64(As, Bs, 0, g_e2, 0, 0, H, 0, p.esw, p.esb, ZD,
                           p.oes + (size_t)t * B * ZD, ZD, (idx - 4) * 64, 0, 2);
                }
            }
            gsync(&gen, false);
        }
        // ---- Phase D: pz(32, fused z = eps*es+em) | z+kld writers(4) ----
        {
            const float* eps_t = p.eps + (size_t)t * B * ZD;
            const float* em_t = p.oem + (size_t)t * B * ZD;
            const float* es_t = p.oes + (size_t)t * B * ZD;
            const float* pm_t = p.opm + (size_t)t * B * ZD;
            const float* ps_t = p.ops + (size_t)t * B * ZD;
            float* z_t = p.oz + (size_t)t * B * ZD;
            float* kld_t = p.okld + (size_t)t * B * ZD;
            for (int idx = blockIdx.x; idx < 36; idx += NBLK) {
                if (idx < 32) {
                    int tm = idx >> 3, tn = idx & 7;
                    gemm64(As, Bs, 2, eps_t, es_t, em_t, ZD, 0, p.pzw, p.pzb, H,
                           g_pz, H, tm * 64, tn * 64, 1);
                } else {
                    int r0 = (idx - 32) * 64;
                    for (int e = threadIdx.x; e < 64 * ZD; e += NTHR) {
                        int o = (r0 + (e >> 6)) * ZD + (e & 63);
                        float em = em_t[o], es = es_t[o], pm = pm_t[o], ps = ps_t[o];
                        float z = eps_t[o] * es + em;
                        z_t[o] = z;
                        float d = em - pm;
                        kld_t[o] = 0.5f * (2.f * logf(ps) - 2.f * logf(es)
                                           + (es * es + d * d) / (ps * ps) - 1.f);
                    }
                }
            }
            gsync(&gen, false);
        }
        // ---- Phase E: d1(32) | gx(96) ----
        {
            for (int idx = blockIdx.x; idx < 128; idx += NBLK) {
                if (idx < 32) {
                    int tm = idx >> 3, tn = idx & 7;
                    gemm64(As, Bs, 1, g_pz, g_h, 0, H, H, p.dw1, p.db1, H, g_d1, H, tm * 64, tn * 64, 1);
                } else {
                    int i2 = idx - 32; int tm = i2 / 24, tn = i2 % 24;
                    gemm64(As, Bs, 1, px, g_pz, 0, H, H, p.gwih, p.gbih, G3, g_gx, G3, tm * 64, tn * 64, 0);
                }
            }
            gsync(&gen, false);
        }
        // ---- Phase F: d2(32) | GRU h update(16) ----
        {
            for (int idx = blockIdx.x; idx < 48; idx += NBLK) {
                if (idx < 32) {
                    int tm = idx >> 3, tn = idx & 7;
                    gemm64(As, Bs, 0, g_d1, 0, 0, H, 0, p.dw2, p.db2, H, g_d2, H, tm * 64, tn * 64, 1);
                } else {
                    int base = (idx - 32) * 8192;
                    for (int e = base + threadIdx.x; e < base + 8192; e += NTHR) {
                        int b = e >> 9, j = e & 511;
                        float xr = g_gx[b * G3 + j], xz = g_gx[b * G3 + 512 + j], xn = g_gx[b * G3 + 1024 + j];
                        float hr = g_gh[b * G3 + j], hz = g_gh[b * G3 + 512 + j], hn = g_gh[b * G3 + 1024 + j];
                        float r = 1.f / (1.f + expf(-(xr + hr)));
                        float u = 1.f / (1.f + expf(-(xz + hz)));
                        float n = tanhf(xn + r * hn);
                        g_h[e] = (1.f - u) * n + u * g_h[e];
                    }
                }
            }
            gsync(&gen, false);
        }
    }
    // ---- logits for final step ----
    for (int idx = blockIdx.x; idx < 16; idx += NBLK) {
        int tm = idx >> 2, tn = idx & 3;
        gemm64(As, Bs, 0, g_d2, 0, 0, H, 0, p.dlw, p.dlb, OD,
               p.olog + (size_t)(T_STEPS - 1) * B * OD, OD, tm * 64, tn * 64, 0);
    }
    gsync(&gen, true);  // resets barrier sense for next graph replay
}

extern "C" void kernel_launch(void* const* d_in, const int* in_sizes, int n_in,
                              void* d_out, int out_size) {
    Params p;
    p.x    = (const float*)d_in[0];
    p.eps  = (const float*)d_in[1];
    p.pxw1 = (const float*)d_in[2];  p.pxb1 = (const float*)d_in[3];
    p.pxw2 = (const float*)d_in[4];  p.pxb2 = (const float*)d_in[5];
    p.pzw  = (const float*)d_in[6];  p.pzb  = (const float*)d_in[7];
    p.ew1  = (const float*)d_in[8];  p.eb1  = (const float*)d_in[9];
    p.ew2  = (const float*)d_in[10]; p.eb2  = (const float*)d_in[11];
    p.emw  = (const float*)d_in[12]; p.emb  = (const float*)d_in[13];
    p.esw  = (const float*)d_in[14]; p.esb  = (const float*)d_in[15];
    p.prw  = (const float*)d_in[16]; p.prb  = (const float*)d_in[17];
    p.pmw  = (const float*)d_in[18]; p.pmb  = (const float*)d_in[19];
    p.psw  = (const float*)d_in[20]; p.psb  = (const float*)d_in[21];
    p.dw1  = (const float*)d_in[22]; p.db1  = (const float*)d_in[23];
    p.dw2  = (const float*)d_in[24]; p.db2  = (const float*)d_in[25];
    p.dlw  = (const float*)d_in[26]; p.dlb  = (const float*)d_in[27];
    // GRU param order is ambiguous (dict vs signature order); disambiguate by size.
    if (in_sizes[29] == 3 * H) {           // dict order: w_ih, b_ih, w_hh, b_hh
        p.gwih = (const float*)d_in[28]; p.gbih = (const float*)d_in[29];
        p.gwhh = (const float*)d_in[30]; p.gbhh = (const float*)d_in[31];
    } else {                               // signature order: w_ih, w_hh, b_ih, b_hh
        p.gwih = (const float*)d_in[28]; p.gwhh = (const float*)d_in[29];
        p.gbih = (const float*)d_in[30]; p.gbhh = (const float*)d_in[31];
    }

    float* o = (float*)d_out;
    size_t TBZ = (size_t)T_STEPS * B * ZD;
    size_t TBO = (size_t)T_STEPS * B * OD;
    p.oz   = o;
    p.olog = o + TBZ;
    p.oem  = p.olog + TBO;
    p.oes  = p.oem + TBZ;
    p.opm  = p.oes + TBZ;
    p.ops  = p.opm + TBZ;
    p.okld = p.ops + TBZ;

    vrnn_kernel<<<NBLK, NTHR>>>(p);
}

// round 2
// speedup vs baseline: 1.6133x; 1.6133x over previous
#include <cuda_runtime.h>
#include <math.h>

#define T_STEPS 200
#define B 256
#define XD 128
#define H 512
#define ZD 64
#define OD 256
#define G3 1536
#define NBLK 148
#define NTHR 256

// smem tile geometry (floats)
#define AS_STRIDE 68            // 32 x 68  (A transposed [k][m], padded)
#define BS_STRIDE 132           // 32 x 132 (W duplicated {w,w} [k][2n], padded)
#define AS_SZ (32 * AS_STRIDE)  // 2176
#define BS_SZ (32 * BS_STRIDE)  // 4224
#define BUF_SZ (AS_SZ + BS_SZ)  // 6400 floats per buffer
#define SMEM_BYTES (2 * BUF_SZ * 4)

// ---------------- scratch ----------------
__device__ float g_phi[(size_t)T_STEPS * B * H];
__device__ float g_tmp[(size_t)T_STEPS * B * H];
__device__ float g_h [B * H];
__device__ float g_pr[B * H];
__device__ float g_e1[B * H];
__device__ float g_e2[B * H];
__device__ float g_pz[B * H];
__device__ float g_d1[B * H];
__device__ float g_d2[B * H];
__device__ float g_gx[B * G3];
__device__ float g_gh[B * G3];

// ---------------- grid barrier ----------------
__device__ unsigned int g_bar = 0;
__device__ volatile unsigned int g_sense = 0;

__device__ __forceinline__ void gsync(unsigned* gen, bool last) {
    __syncthreads();
    if (threadIdx.x == 0) {
        __threadfence();
        unsigned g = *gen;
        if (atomicAdd(&g_bar, 1u) == (unsigned)(NBLK - 1)) {
            g_bar = 0u;
            __threadfence();
            g_sense = last ? 0u : (g + 1u);
        } else {
            while (g_sense == g) { __nanosleep(32); }
            __threadfence();
        }
    }
    __syncthreads();
    (*gen)++;
}

// ---------------- helpers ----------------
__device__ __forceinline__ unsigned long long pk2(float x, float y) {
    unsigned long long r;
    asm("mov.b64 %0, {%1,%2};" : "=l"(r) : "f"(x), "f"(y));
    return r;
}
__device__ __forceinline__ float2 upk2(unsigned long long v) {
    float2 r;
    asm("mov.b64 {%0,%1}, %2;" : "=f"(r.x), "=f"(r.y) : "l"(v));
    return r;
}
__device__ __forceinline__ void ffma2(unsigned long long& d, unsigned long long a, unsigned long long b) {
    asm("fma.rn.f32x2 %0, %1, %2, %0;" : "+l"(d) : "l"(a), "l"(b));
}
__device__ __forceinline__ float actf(float v, int act) {
    if (act == 1) return fmaxf(v, 0.f);
    if (act == 2) return fmaxf(v, 0.f) + log1pf(expf(-fabsf(v)));
    return v;
}

// ---------------- 64x64 tile GEMM, fp32 via f32x2, double-buffered ----------------
// amode 0: A = A0 [rows x k0]
// amode 1: A = concat(A0 [rows x k0], A1 [rows x k1])
// amode 2: A[r,k] = A0[r*k0+k]*A1[r*k0+k] + A2[r*k0+k]   (K = k0)
__device__ __noinline__ void gemm64(
    float* sm, int amode,
    const float* __restrict__ A0, const float* __restrict__ A1, const float* __restrict__ A2,
    int k0, int k1,
    const float* __restrict__ W, const float* __restrict__ bias, int N,
    float* __restrict__ C, int ldc, int row0, int col0, int act)
{
    const int tid = threadIdx.x;
    const int tx = tid & 15, ty = tid >> 4;
    const int K = k0 + k1, KT = K >> 5;

    // staging decomposition
    const int am = tid >> 3;              // 0..31  (A row, +32 for l=1)
    const int ak4 = tid & 7;              // 0..7   (A k-quad)
    const int wkk = tid >> 4;             // 0..15  (W k row, +16 for l=1)
    const int wn4 = tid & 15;             // 0..15  (W n-quad)

    unsigned long long acc[2][4];
#pragma unroll
    for (int i = 0; i < 2; i++)
#pragma unroll
        for (int j = 0; j < 4; j++) acc[i][j] = 0ULL;

    float4 ra[2], rw[2];

    auto loadA = [&](int kb, int l) -> float4 {
        int m = am + l * 32;
        int k = kb + ak4 * 4;
        int r = row0 + m;
        if (amode == 2) {
            int o = r * k0 + k;
            float4 a = *(const float4*)(A0 + o);
            float4 s = *(const float4*)(A1 + o);
            float4 mu = *(const float4*)(A2 + o);
            return make_float4(fmaf(a.x, s.x, mu.x), fmaf(a.y, s.y, mu.y),
                               fmaf(a.z, s.z, mu.z), fmaf(a.w, s.w, mu.w));
        } else if (k < k0) {
            return *(const float4*)(A0 + r * k0 + k);
        } else {
            return *(const float4*)(A1 + r * k1 + (k - k0));
        }
    };
    auto loadW = [&](int kb, int l) -> float4 {
        int kk = wkk + l * 16;
        return *(const float4*)(W + (size_t)(kb + kk) * N + col0 + 4 * wn4);
    };
    auto stsAll = [&](float* buf) {
        float* As = buf;
        float* Bs = buf + AS_SZ;
#pragma unroll
        for (int l = 0; l < 2; l++) {
            int m = am + l * 32;
            float4 v = ra[l];
            As[(ak4 * 4 + 0) * AS_STRIDE + m] = v.x;
            As[(ak4 * 4 + 1) * AS_STRIDE + m] = v.y;
            As[(ak4 * 4 + 2) * AS_STRIDE + m] = v.z;
            As[(ak4 * 4 + 3) * AS_STRIDE + m] = v.w;
            int kk = wkk + l * 16;
            float2* p = (float2*)(Bs + kk * BS_STRIDE + 8 * wn4);
            float4 w = rw[l];
            p[0] = make_float2(w.x, w.x);
            p[1] = make_float2(w.y, w.y);
            p[2] = make_float2(w.z, w.z);
            p[3] = make_float2(w.w, w.w);
        }
    };

    // prologue: stage k-tile 0
    ra[0] = loadA(0, 0); ra[1] = loadA(0, 1);
    rw[0] = loadW(0, 0); rw[1] = loadW(0, 1);
    stsAll(sm);
    __syncthreads();

    int cur = 0;
    for (int kt = 0; kt < KT; kt++) {
        if (kt + 1 < KT) {
            int kb = (kt + 1) * 32;
            ra[0] = loadA(kb, 0); ra[1] = loadA(kb, 1);
            rw[0] = loadW(kb, 0); rw[1] = loadW(kb, 1);
        }
        const float* As = sm + cur * BUF_SZ;
        const float* Bs = As + AS_SZ;
#pragma unroll
        for (int kk = 0; kk < 32; kk++) {
            float4 a4 = *(const float4*)(As + kk * AS_STRIDE + 4 * ty);
            unsigned long long A01 = pk2(a4.x, a4.y);
            unsigned long long A23 = pk2(a4.z, a4.w);
            float4 b0 = *(const float4*)(Bs + kk * BS_STRIDE + 8 * tx);
            float4 b1 = *(const float4*)(Bs + kk * BS_STRIDE + 8 * tx + 4);
            unsigned long long Bd0 = pk2(b0.x, b0.y);
            unsigned long long Bd1 = pk2(b0.z, b0.w);
            unsigned long long Bd2 = pk2(b1.x, b1.y);
            unsigned long long Bd3 = pk2(b1.z, b1.w);
            ffma2(acc[0][0], A01, Bd0); ffma2(acc[1][0], A23, Bd0);
            ffma2(acc[0][1], A01, Bd1); ffma2(acc[1][1], A23, Bd1);
            ffma2(acc[0][2], A01, Bd2); ffma2(acc[1][2], A23, Bd2);
            ffma2(acc[0][3], A01, Bd3); ffma2(acc[1][3], A23, Bd3);
        }
        if (kt + 1 < KT) stsAll(sm + (cur ^ 1) * BUF_SZ);
        __syncthreads();
        cur ^= 1;
    }

    // epilogue
    float4 bias4 = *(const float4*)(bias + col0 + 4 * tx);
    float bj[4] = {bias4.x, bias4.y, bias4.z, bias4.w};
    float2 u[2][4];
#pragma unroll
    for (int i = 0; i < 2; i++)
#pragma unroll
        for (int j = 0; j < 4; j++) u[i][j] = upk2(acc[i][j]);
#pragma unroll
    for (int rr = 0; rr < 4; rr++) {
        int ip = rr >> 1, hh = rr & 1;
        float4 o;
        o.x = actf((hh ? u[ip][0].y : u[ip][0].x) + bj[0], act);
        o.y = actf((hh ? u[ip][1].y : u[ip][1].x) + bj[1], act);
        o.z = actf((hh ? u[ip][2].y : u[ip][2].x) + bj[2], act);
        o.w = actf((hh ? u[ip][3].y : u[ip][3].x) + bj[3], act);
        *(float4*)(C + (size_t)(row0 + 4 * ty + rr) * ldc + col0 + 4 * tx) = o;
    }
}

// ---------------- params ----------------
struct Params {
    const float *x, *eps;
    const float *pxw1, *pxb1, *pxw2, *pxb2;
    const float *pzw, *pzb;
    const float *ew1, *eb1, *ew2, *eb2, *emw, *emb, *esw, *esb;
    const float *prw, *prb, *pmw, *pmb, *psw, *psb;
    const float *dw1, *db1, *dw2, *db2, *dlw, *dlb;
    const float *gwih, *gbih, *gwhh, *gbhh;
    float *oz, *olog, *oem, *oes, *opm, *ops, *okld;
};

__global__ void __launch_bounds__(NTHR) vrnn_kernel(Params p) {
    extern __shared__ float sm[];
    unsigned gen = 0;

    for (int e = blockIdx.x * NTHR + threadIdx.x; e < B * H; e += NBLK * NTHR) g_h[e] = 0.f;

    // ---- phi_x (all timesteps) ----
    for (int idx = blockIdx.x; idx < (T_STEPS * B / 64) * 8; idx += NBLK) {
        int tm = idx >> 3, tn = idx & 7;
        gemm64(sm, 0, p.x, 0, 0, XD, 0, p.pxw1, p.pxb1, H, g_tmp, H, tm * 64, tn * 64, 1);
    }
    gsync(&gen, false);
    for (int idx = blockIdx.x; idx < (T_STEPS * B / 64) * 8; idx += NBLK) {
        int tm = idx >> 3, tn = idx & 7;
        gemm64(sm, 0, g_tmp, 0, 0, H, 0, p.pxw2, p.pxb2, H, g_phi, H, tm * 64, tn * 64, 1);
    }
    gsync(&gen, false);

    for (int t = 0; t < T_STEPS; t++) {
        const float* px = g_phi + (size_t)t * B * H;

        // ---- Phase A: e1(0..31, K=1024) | gh(32..127) | pr(128..159) | logits[t-1](160..175)
        {
            int nt = 160 + (t > 0 ? 16 : 0);
#pragma unroll 1
            for (int r = 0; r < 2; r++) {
                int idx = (r == 0) ? (int)blockIdx.x : (NBLK + (NBLK - 1 - (int)blockIdx.x));
                if (idx >= nt) continue;
                if (idx < 32) {
                    int tm = idx >> 3, tn = idx & 7;
                    gemm64(sm, 1, px, g_h, 0, H, H, p.ew1, p.eb1, H, g_e1, H, tm * 64, tn * 64, 1);
                } else if (idx < 128) {
                    int i2 = idx - 32; int tm = i2 / 24, tn = i2 % 24;
                    gemm64(sm, 0, g_h, 0, 0, H, 0, p.gwhh, p.gbhh, G3, g_gh, G3, tm * 64, tn * 64, 0);
                } else if (idx < 160) {
                    int i2 = idx - 128; int tm = i2 >> 3, tn = i2 & 7;
                    gemm64(sm, 0, g_h, 0, 0, H, 0, p.prw, p.prb, H, g_pr, H, tm * 64, tn * 64, 1);
                } else {
                    int i2 = idx - 160; int tm = i2 >> 2, tn = i2 & 3;
                    gemm64(sm, 0, g_d2, 0, 0, H, 0, p.dlw, p.dlb, OD,
                           p.olog + (size_t)(t - 1) * B * OD, OD, tm * 64, tn * 64, 0);
                }
            }
            gsync(&gen, false);
        }
        // ---- Phase B: e2(32) | pm(4) | ps(4)
        {
            int idx = blockIdx.x;
            if (idx < 40) {
                if (idx < 32) {
                    int tm = idx >> 3, tn = idx & 7;
                    gemm64(sm, 0, g_e1, 0, 0, H, 0, p.ew2, p.eb2, H, g_e2, H, tm * 64, tn * 64, 1);
                } else if (idx < 36) {
                    int tm = idx - 32;
                    gemm64(sm, 0, g_pr, 0, 0, H, 0, p.pmw, p.pmb, ZD,
                           p.opm + (size_t)t * B * ZD, ZD, tm * 64, 0, 0);
                } else {
                    int tm = idx - 36;
                    gemm64(sm, 0, g_pr, 0, 0, H, 0, p.psw, p.psb, ZD,
                           p.ops + (size_t)t * B * ZD, ZD, tm * 64, 0, 2);
                }
            }
            gsync(&gen, false);
        }
        // ---- Phase C: em(4) | es(4)
        {
            int idx = blockIdx.x;
            if (idx < 8) {
                if (idx < 4) {
                    gemm64(sm, 0, g_e2, 0, 0, H, 0, p.emw, p.emb, ZD,
                           p.oem + (size_t)t * B * ZD, ZD, idx * 64, 0, 0);
                } else {
                    gemm64(sm, 0, g_e2, 0, 0, H, 0, p.esw, p.esb, ZD,
                           p.oes + (size_t)t * B * ZD, ZD, (idx - 4) * 64, 0, 2);
                }
            }
            gsync(&gen, false);
        }
        // ---- Phase D: pz(32, K=64 fused z) | z+kld(4)
        {
            const float* eps_t = p.eps + (size_t)t * B * ZD;
            const float* em_t = p.oem + (size_t)t * B * ZD;
            const float* es_t = p.oes + (size_t)t * B * ZD;
            const float* pm_t = p.opm + (size_t)t * B * ZD;
            const float* ps_t = p.ops + (size_t)t * B * ZD;
            float* z_t = p.oz + (size_t)t * B * ZD;
            float* kld_t = p.okld + (size_t)t * B * ZD;
            int idx = blockIdx.x;
            if (idx < 36) {
                if (idx < 32) {
                    int tm = idx >> 3, tn = idx & 7;
                    gemm64(sm, 2, eps_t, es_t, em_t, ZD, 0, p.pzw, p.pzb, H,
                           g_pz, H, tm * 64, tn * 64, 1);
                } else {
                    int r0 = (idx - 32) * 64;
                    for (int e = threadIdx.x; e < 64 * ZD; e += NTHR) {
                        int o = (r0 + (e >> 6)) * ZD + (e & 63);
                        float em = em_t[o], es = es_t[o], pm = pm_t[o], ps = ps_t[o];
                        z_t[o] = eps_t[o] * es + em;
                        float d = em - pm;
                        kld_t[o] = 0.5f * (2.f * logf(ps) - 2.f * logf(es)
                                           + (es * es + d * d) / (ps * ps) - 1.f);
                    }
                }
            }
            gsync(&gen, false);
        }
        // ---- Phase E: gx(0..95, K=1024) | d1(96..127, K=1024)
        {
            int idx = blockIdx.x;
            if (idx < 128) {
                if (idx < 96) {
                    int tm = idx / 24, tn = idx % 24;
                    gemm64(sm, 1, px, g_pz, 0, H, H, p.gwih, p.gbih, G3, g_gx, G3, tm * 64, tn * 64, 0);
                } else {
                    int i2 = idx - 96; int tm = i2 >> 3, tn = i2 & 7;
                    gemm64(sm, 1, g_pz, g_h, 0, H, H, p.dw1, p.db1, H, g_d1, H, tm * 64, tn * 64, 1);
                }
            }
            gsync(&gen, false);
        }
        // ---- Phase F: d2(32) | GRU(16)
        {
            int idx = blockIdx.x;
            if (idx < 48) {
                if (idx < 32) {
                    int tm = idx >> 3, tn = idx & 7;
                    gemm64(sm, 0, g_d1, 0, 0, H, 0, p.dw2, p.db2, H, g_d2, H, tm * 64, tn * 64, 1);
                } else {
                    int base = (idx - 32) * 8192;
                    for (int e = base + threadIdx.x; e < base + 8192; e += NTHR) {
                        int b = e >> 9, j = e & 511;
                        float xr = g_gx[b * G3 + j], xz = g_gx[b * G3 + 512 + j], xn = g_gx[b * G3 + 1024 + j];
                        float hr = g_gh[b * G3 + j], hz = g_gh[b * G3 + 512 + j], hn = g_gh[b * G3 + 1024 + j];
                        float rg = 1.f / (1.f + expf(-(xr + hr)));
                        float ug = 1.f / (1.f + expf(-(xz + hz)));
                        float ng = tanhf(xn + rg * hn);
                        g_h[e] = (1.f - ug) * ng + ug * g_h[e];
                    }
                }
            }
            gsync(&gen, false);
        }
    }
    // final logits
    {
        int idx = blockIdx.x;
        if (idx < 16) {
            int tm = idx >> 2, tn = idx & 3;
            gemm64(sm, 0, g_d2, 0, 0, H, 0, p.dlw, p.dlb, OD,
                   p.olog + (size_t)(T_STEPS - 1) * B * OD, OD, tm * 64, tn * 64, 0);
        }
    }
    gsync(&gen, true);
}

extern "C" void kernel_launch(void* const* d_in, const int* in_sizes, int n_in,
                              void* d_out, int out_size) {
    Params p;
    p.x    = (const float*)d_in[0];
    p.eps  = (const float*)d_in[1];
    p.pxw1 = (const float*)d_in[2];  p.pxb1 = (const float*)d_in[3];
    p.pxw2 = (const float*)d_in[4];  p.pxb2 = (const float*)d_in[5];
    p.pzw  = (const float*)d_in[6];  p.pzb  = (const float*)d_in[7];
    p.ew1  = (const float*)d_in[8];  p.eb1  = (const float*)d_in[9];
    p.ew2  = (const float*)d_in[10]; p.eb2  = (const float*)d_in[11];
    p.emw  = (const float*)d_in[12]; p.emb  = (const float*)d_in[13];
    p.esw  = (const float*)d_in[14]; p.esb  = (const float*)d_in[15];
    p.prw  = (const float*)d_in[16]; p.prb  = (const float*)d_in[17];
    p.pmw  = (const float*)d_in[18]; p.pmb  = (const float*)d_in[19];
    p.psw  = (const float*)d_in[20]; p.psb  = (const float*)d_in[21];
    p.dw1  = (const float*)d_in[22]; p.db1  = (const float*)d_in[23];
    p.dw2  = (const float*)d_in[24]; p.db2  = (const float*)d_in[25];
    p.dlw  = (const float*)d_in[26]; p.dlb  = (const float*)d_in[27];
    if (in_sizes[29] == 3 * H) {
        p.gwih = (const float*)d_in[28]; p.gbih = (const float*)d_in[29];
        p.gwhh = (const float*)d_in[30]; p.gbhh = (const float*)d_in[31];
    } else {
        p.gwih = (const float*)d_in[28]; p.gwhh = (const float*)d_in[29];
        p.gbih = (const float*)d_in[30]; p.gbhh = (const float*)d_in[31];
    }

    float* o = (float*)d_out;
    size_t TBZ = (size_t)T_STEPS * B * ZD;
    size_t TBO = (size_t)T_STEPS * B * OD;
    p.oz   = o;
    p.olog = o + TBZ;
    p.oem  = p.olog + TBO;
    p.oes  = p.oem + TBZ;
    p.opm  = p.oes + TBZ;
    p.ops  = p.opm + TBZ;
    p.okld = p.ops + TBZ;

    static bool attr_set = false;
    if (!attr_set) {
        cudaFuncSetAttribute(vrnn_kernel, cudaFuncAttributeMaxDynamicSharedMemorySize, SMEM_BYTES);
        attr_set = true;
    }
    vrnn_kernel<<<NBLK, NTHR, SMEM_BYTES>>>(p);
}

// round 3
// speedup vs baseline: 2.2043x; 1.3663x over previous
#include <cuda_runtime.h>
#include <math.h>

#define T_STEPS 200
#define B 256
#define XD 128
#define H 512
#define ZD 64
#define OD 256
#define G3 1536
#define NBLK 148
#define NTHR 512
#define UN 4
#define UT 128
#define NUNITS (NBLK * UN)   // 592

// per-unit smem tile geometry (floats)
#define AS_STRIDE 68
#define BS_STRIDE 68
#define AS_SZ (32 * AS_STRIDE)
#define BS_SZ (32 * BS_STRIDE)
#define BUF_SZ (AS_SZ + BS_SZ)               // 4352 floats
#define UNIT_SM (2 * BUF_SZ)                 // double buffered
#define SMEM_BYTES (UN * UNIT_SM * 4)        // ~139.3 KB

// ---------------- scratch ----------------
__device__ float g_phi[(size_t)T_STEPS * B * H];
__device__ float g_tmp[(size_t)T_STEPS * B * H];
__device__ float g_h [B * H];
__device__ float g_pr[B * H];
__device__ float g_e1[B * H];
__device__ float g_e2[B * H];
__device__ float g_pz[B * H];
__device__ float g_d1b[2][B * H];
__device__ float g_d2[B * H];
__device__ float g_gx[B * G3];
__device__ float g_gh[B * G3];

// ---------------- grid barrier ----------------
__device__ unsigned int g_bar = 0;
__device__ volatile unsigned int g_sense = 0;

__device__ __forceinline__ void gsync(unsigned* gen, bool last) {
    __syncthreads();
    if (threadIdx.x == 0) {
        __threadfence();
        unsigned g = *gen;
        if (atomicAdd(&g_bar, 1u) == (unsigned)(NBLK - 1)) {
            g_bar = 0u;
            __threadfence();
            g_sense = last ? 0u : (g + 1u);
        } else {
            while (g_sense == g) { __nanosleep(32); }
            __threadfence();
        }
    }
    __syncthreads();
    (*gen)++;
}

__device__ __forceinline__ void ubar(int id) {
    asm volatile("bar.sync %0, %1;" :: "r"(id), "r"(UT) : "memory");
}

// ---------------- helpers ----------------
__device__ __forceinline__ unsigned long long pk2(float x, float y) {
    unsigned long long r;
    asm("mov.b64 %0, {%1,%2};" : "=l"(r) : "f"(x), "f"(y));
    return r;
}
__device__ __forceinline__ float2 upk2(unsigned long long v) {
    float2 r;
    asm("mov.b64 {%0,%1}, %2;" : "=f"(r.x), "=f"(r.y) : "l"(v));
    return r;
}
__device__ __forceinline__ void ffma2(unsigned long long& d, unsigned long long a, unsigned long long b) {
    asm("fma.rn.f32x2 %0, %1, %2, %0;" : "+l"(d) : "l"(a), "l"(b));
}
__device__ __forceinline__ float actf(float v, int act) {
    if (act == 1) return fmaxf(v, 0.f);
    if (act == 2) return fmaxf(v, 0.f) + log1pf(expf(-fabsf(v)));
    return v;
}

// ---------------- 64x64 tile GEMM on a 128-thread unit ----------------
// per-thread: 8 rows x 4 cols. amode 0 plain / 1 concat / 2 z=eps*es+em.
// accum: C = act(C_old + A@W)  (no bias);  else C = act(A@W + bias)
__device__ __noinline__ void gemm64u(
    float* us, int ut, int barid, int amode,
    const float* __restrict__ A0, const float* __restrict__ A1, const float* __restrict__ A2,
    int k0, int k1,
    const float* __restrict__ W, const float* __restrict__ bias, int N,
    float* __restrict__ C, int ldc, int row0, int col0, int act, int accum)
{
    const int tx = ut & 15, ty = ut >> 4;
    const int KT = (k0 + k1) >> 5;

    unsigned long long acc[4][4];
#pragma unroll
    for (int i = 0; i < 4; i++)
#pragma unroll
        for (int j = 0; j < 4; j++) acc[i][j] = 0ULL;

    float4 ra[4], rb[4];

    auto ldA = [&](int kb, int l) -> float4 {
        int idx = ut + (l << 7);
        int r = row0 + (idx >> 3);
        int k = kb + ((idx & 7) << 2);
        if (amode == 2) {
            int o = r * k0 + k;
            float4 a = *(const float4*)(A0 + o);
            float4 s = *(const float4*)(A1 + o);
            float4 m = *(const float4*)(A2 + o);
            return make_float4(fmaf(a.x, s.x, m.x), fmaf(a.y, s.y, m.y),
                               fmaf(a.z, s.z, m.z), fmaf(a.w, s.w, m.w));
        } else if (k < k0) {
            return *(const float4*)(A0 + (size_t)r * k0 + k);
        } else {
            return *(const float4*)(A1 + (size_t)r * k1 + (k - k0));
        }
    };
    auto ldB = [&](int kb, int l) -> float4 {
        int idx = ut + (l << 7);
        int k = kb + (idx >> 4);
        int n = col0 + ((idx & 15) << 2);
        return *(const float4*)(W + (size_t)k * N + n);
    };
    auto stAll = [&](float* buf) {
        float* As = buf;
        float* Bs = buf + AS_SZ;
#pragma unroll
        for (int l = 0; l < 4; l++) {
            int idx = ut + (l << 7);
            int r = idx >> 3, kq = (idx & 7) << 2;
            float4 v = ra[l];
            As[(kq + 0) * AS_STRIDE + r] = v.x;
            As[(kq + 1) * AS_STRIDE + r] = v.y;
            As[(kq + 2) * AS_STRIDE + r] = v.z;
            As[(kq + 3) * AS_STRIDE + r] = v.w;
            int k = idx >> 4, n4 = (idx & 15) << 2;
            *(float4*)(Bs + k * BS_STRIDE + n4) = rb[l];
        }
    };

    // prologue
#pragma unroll
    for (int l = 0; l < 4; l++) { ra[l] = ldA(0, l); rb[l] = ldB(0, l); }
    stAll(us);
    ubar(barid);

    int cur = 0;
    for (int kt = 0; kt < KT; kt++) {
        if (kt + 1 < KT) {
            int kb = (kt + 1) << 5;
#pragma unroll
            for (int l = 0; l < 4; l++) { ra[l] = ldA(kb, l); rb[l] = ldB(kb, l); }
        }
        const float* As = us + cur * BUF_SZ;
        const float* Bs = As + AS_SZ;
#pragma unroll 8
        for (int kk = 0; kk < 32; kk++) {
            float4 a0 = *(const float4*)(As + kk * AS_STRIDE + 8 * ty);
            float4 a1 = *(const float4*)(As + kk * AS_STRIDE + 8 * ty + 4);
            float4 b  = *(const float4*)(Bs + kk * BS_STRIDE + 4 * tx);
            unsigned long long A01 = pk2(a0.x, a0.y);
            unsigned long long A23 = pk2(a0.z, a0.w);
            unsigned long long A45 = pk2(a1.x, a1.y);
            unsigned long long A67 = pk2(a1.z, a1.w);
            unsigned long long B0 = pk2(b.x, b.x);
            unsigned long long B1 = pk2(b.y, b.y);
            unsigned long long B2 = pk2(b.z, b.z);
            unsigned long long B3 = pk2(b.w, b.w);
            ffma2(acc[0][0], A01, B0); ffma2(acc[1][0], A23, B0);
            ffma2(acc[2][0], A45, B0); ffma2(acc[3][0], A67, B0);
            ffma2(acc[0][1], A01, B1); ffma2(acc[1][1], A23, B1);
            ffma2(acc[2][1], A45, B1); ffma2(acc[3][1], A67, B1);
            ffma2(acc[0][2], A01, B2); ffma2(acc[1][2], A23, B2);
            ffma2(acc[2][2], A45, B2); ffma2(acc[3][2], A67, B2);
            ffma2(acc[0][3], A01, B3); ffma2(acc[1][3], A23, B3);
            ffma2(acc[2][3], A45, B3); ffma2(acc[3][3], A67, B3);
        }
        if (kt + 1 < KT) stAll(us + (cur ^ 1) * BUF_SZ);
        ubar(barid);
        cur ^= 1;
    }

    // epilogue
    float4 b4 = accum ? make_float4(0.f, 0.f, 0.f, 0.f)
                      : *(const float4*)(bias + col0 + 4 * tx);
#pragma unroll
    for (int i = 0; i < 4; i++) {
        float2 u0 = upk2(acc[i][0]), u1 = upk2(acc[i][1]);
        float2 u2 = upk2(acc[i][2]), u3 = upk2(acc[i][3]);
        float* c0 = C + (size_t)(row0 + 8 * ty + 2 * i) * ldc + col0 + 4 * tx;
        float* c1 = c0 + ldc;
        float4 oA = make_float4(u0.x + b4.x, u1.x + b4.y, u2.x + b4.z, u3.x + b4.w);
        float4 oB = make_float4(u0.y + b4.x, u1.y + b4.y, u2.y + b4.z, u3.y + b4.w);
        if (accum) {
            float4 e0 = *(float4*)c0, e1 = *(float4*)c1;
            oA.x += e0.x; oA.y += e0.y; oA.z += e0.z; oA.w += e0.w;
            oB.x += e1.x; oB.y += e1.y; oB.z += e1.z; oB.w += e1.w;
        }
        oA.x = actf(oA.x, act); oA.y = actf(oA.y, act); oA.z = actf(oA.z, act); oA.w = actf(oA.w, act);
        oB.x = actf(oB.x, act); oB.y = actf(oB.y, act); oB.z = actf(oB.z, act); oB.w = actf(oB.w, act);
        *(float4*)c0 = oA;
        *(float4*)c1 = oB;
    }
}

// ---------------- params ----------------
struct Params {
    const float *x, *eps;
    const float *pxw1, *pxb1, *pxw2, *pxb2;
    const float *pzw, *pzb;
    const float *ew1, *eb1, *ew2, *eb2, *emw, *emb, *esw, *esb;
    const float *prw, *prb, *pmw, *pmb, *psw, *psb;
    const float *dw1, *db1, *dw2, *db2, *dlw, *dlb;
    const float *gwih, *gbih, *gwhh, *gbhh;
    float *oz, *olog, *oem, *oes, *opm, *ops, *okld;
};

__global__ void __launch_bounds__(NTHR, 1) vrnn_kernel(Params p) {
    extern __shared__ float sm[];
    unsigned gen = 0;
    const int u = threadIdx.x >> 7;        // unit 0..3
    const int ut = threadIdx.x & 127;
    const int barid = u + 1;
    float* us = sm + u * UNIT_SM;
    const int blk = blockIdx.x;
    const int uid = u * NBLK + blk;

    for (int e = blk * NTHR + threadIdx.x; e < B * H; e += NBLK * NTHR) g_h[e] = 0.f;

    // ---- phi_x (all timesteps): 6400 tasks each stage ----
    for (int idx = uid; idx < (T_STEPS * B / 64) * 8; idx += NUNITS) {
        int tm = idx >> 3, tn = idx & 7;
        gemm64u(us, ut, barid, 0, p.x, 0, 0, XD, 0, p.pxw1, p.pxb1, H,
                g_tmp, H, tm * 64, tn * 64, 1, 0);
    }
    gsync(&gen, false);
    for (int idx = uid; idx < (T_STEPS * B / 64) * 8; idx += NUNITS) {
        int tm = idx >> 3, tn = idx & 7;
        gemm64u(us, ut, barid, 0, g_tmp, 0, 0, H, 0, p.pxw2, p.pxb2, H,
                g_phi, H, tm * 64, tn * 64, 1, 0);
    }
    gsync(&gen, false);

    for (int t = 0; t < T_STEPS; t++) {
        const float* px = g_phi + (size_t)t * B * H;
        float* d1 = g_d1b[t & 1];
        const float* d1prev = g_d1b[(t ^ 1) & 1];

        // ---- P1: e1(K=1024) | gh | gx_px | d1_h | pr | d2(t-1) ----
        {
            int nlight = (t > 0) ? 288 : 256;
            int task = -1;               // 0..31 = e1, >=32 = light (task-32)
            if (blk < 32) {
                if (u == 0) task = blk;
                else if (u == 1) task = 32 + blk;
            } else if (u >= 1) {
                int L = 32 + (u - 1) * 116 + (blk - 32);
                if (L < nlight) task = 32 + L;
            }
            if (task >= 0) {
                if (task < 32) {
                    int tm = task >> 3, tn = task & 7;
                    gemm64u(us, ut, barid, 1, px, g_h, 0, H, H, p.ew1, p.eb1, H,
                            g_e1, H, tm * 64, tn * 64, 1, 0);
                } else {
                    int L = task - 32;
                    if (L < 96) {                       // gh
                        int tm = L / 24, tn = L % 24;
                        gemm64u(us, ut, barid, 0, g_h, 0, 0, H, 0, p.gwhh, p.gbhh, G3,
                                g_gh, G3, tm * 64, tn * 64, 0, 0);
                    } else if (L < 192) {               // gx_px (top half of gwih)
                        int i = L - 96; int tm = i / 24, tn = i % 24;
                        gemm64u(us, ut, barid, 0, px, 0, 0, H, 0, p.gwih, p.gbih, G3,
                                g_gx, G3, tm * 64, tn * 64, 0, 0);
                    } else if (L < 224) {               // d1_h (bottom half of dw1)
                        int i = L - 192; int tm = i >> 3, tn = i & 7;
                        gemm64u(us, ut, barid, 0, g_h, 0, 0, H, 0, p.dw1 + (size_t)H * H, p.db1, H,
                                d1, H, tm * 64, tn * 64, 0, 0);
                    } else if (L < 256) {               // pr
                        int i = L - 224; int tm = i >> 3, tn = i & 7;
                        gemm64u(us, ut, barid, 0, g_h, 0, 0, H, 0, p.prw, p.prb, H,
                                g_pr, H, tm * 64, tn * 64, 1, 0);
                    } else {                            // d2(t-1)
                        int i = L - 256; int tm = i >> 3, tn = i & 7;
                        gemm64u(us, ut, barid, 0, d1prev, 0, 0, H, 0, p.dw2, p.db2, H,
                                g_d2, H, tm * 64, tn * 64, 1, 0);
                    }
                }
            }
            gsync(&gen, false);
        }
        // ---- P2: e2(32) | pm(4) | ps(4) | logits(t-1)(16) ----
        {
            int nt = 40 + (t > 0 ? 16 : 0);
            int idx = uid;
            if (idx < nt) {
                if (idx < 32) {
                    int tm = idx >> 3, tn = idx & 7;
                    gemm64u(us, ut, barid, 0, g_e1, 0, 0, H, 0, p.ew2, p.eb2, H,
                            g_e2, H, tm * 64, tn * 64, 1, 0);
                } else if (idx < 36) {
                    gemm64u(us, ut, barid, 0, g_pr, 0, 0, H, 0, p.pmw, p.pmb, ZD,
                            p.opm + (size_t)t * B * ZD, ZD, (idx - 32) * 64, 0, 0, 0);
                } else if (idx < 40) {
                    gemm64u(us, ut, barid, 0, g_pr, 0, 0, H, 0, p.psw, p.psb, ZD,
                            p.ops + (size_t)t * B * ZD, ZD, (idx - 36) * 64, 0, 2, 0);
                } else {
                    int i = idx - 40; int tm = i >> 2, tn = i & 3;
                    gemm64u(us, ut, barid, 0, g_d2, 0, 0, H, 0, p.dlw, p.dlb, OD,
                            p.olog + (size_t)(t - 1) * B * OD, OD, tm * 64, tn * 64, 0, 0);
                }
            }
            gsync(&gen, false);
        }
        // ---- P3: em(4) | es(4) ----
        {
            int idx = uid;
            if (idx < 8) {
                if (idx < 4)
                    gemm64u(us, ut, barid, 0, g_e2, 0, 0, H, 0, p.emw, p.emb, ZD,
                            p.oem + (size_t)t * B * ZD, ZD, idx * 64, 0, 0, 0);
                else
                    gemm64u(us, ut, barid, 0, g_e2, 0, 0, H, 0, p.esw, p.esb, ZD,
                            p.oes + (size_t)t * B * ZD, ZD, (idx - 4) * 64, 0, 2, 0);
            }
            gsync(&gen, false);
        }
        // ---- P4: pz(32, K=64 fused z) | z+kld(4) ----
        {
            const float* eps_t = p.eps + (size_t)t * B * ZD;
            const float* em_t = p.oem + (size_t)t * B * ZD;
            const float* es_t = p.oes + (size_t)t * B * ZD;
            const float* pm_t = p.opm + (size_t)t * B * ZD;
            const float* ps_t = p.ops + (size_t)t * B * ZD;
            float* z_t = p.oz + (size_t)t * B * ZD;
            float* kld_t = p.okld + (size_t)t * B * ZD;
            int idx = uid;
            if (idx < 36) {
                if (idx < 32) {
                    int tm = idx >> 3, tn = idx & 7;
                    gemm64u(us, ut, barid, 2, eps_t, es_t, em_t, ZD, 0, p.pzw, p.pzb, H,
                            g_pz, H, tm * 64, tn * 64, 1, 0);
                } else {
                    int r0 = (idx - 32) * 64;
                    for (int e = ut; e < 64 * ZD; e += UT) {
                        int o = (r0 + (e >> 6)) * ZD + (e & 63);
                        float em = em_t[o], es = es_t[o], pm = pm_t[o], ps = ps_t[o];
                        z_t[o] = eps_t[o] * es + em;
                        float d = em - pm;
                        kld_t[o] = 0.5f * (2.f * logf(ps) - 2.f * logf(es)
                                           + (es * es + d * d) / (ps * ps) - 1.f);
                    }
                }
            }
            gsync(&gen, false);
        }
        // ---- P5: gx += pz@gwih_bot (96) | d1 = relu(d1 + pz@dw1_top) (32) ----
        {
            int idx = uid;
            if (idx < 128) {
                if (idx < 96) {
                    int tm = idx / 24, tn = idx % 24;
                    gemm64u(us, ut, barid, 0, g_pz, 0, 0, H, 0, p.gwih + (size_t)H * G3, 0, G3,
                            g_gx, G3, tm * 64, tn * 64, 0, 1);
                } else {
                    int i = idx - 96; int tm = i >> 3, tn = i & 7;
                    gemm64u(us, ut, barid, 0, g_pz, 0, 0, H, 0, p.dw1, 0, H,
                            d1, H, tm * 64, tn * 64, 1, 1);
                }
            }
            gsync(&gen, false);
        }
        // ---- P6: GRU h update (16) ----
        {
            int idx = uid;
            if (idx < 16) {
                int base = idx * 8192;
                for (int e = base + ut; e < base + 8192; e += UT) {
                    int b = e >> 9, j = e & 511;
                    float xr = g_gx[b * G3 + j], xz = g_gx[b * G3 + 512 + j], xn = g_gx[b * G3 + 1024 + j];
                    float hr = g_gh[b * G3 + j], hz = g_gh[b * G3 + 512 + j], hn = g_gh[b * G3 + 1024 + j];
                    float rg = 1.f / (1.f + expf(-(xr + hr)));
                    float ug = 1.f / (1.f + expf(-(xz + hz)));
                    float ng = tanhf(xn + rg * hn);
                    g_h[e] = (1.f - ug) * ng + ug * g_h[e];
                }
            }
            gsync(&gen, false);
        }
    }
    // ---- tail: d2(199), then logits(199) ----
    {
        int idx = uid;
        if (idx < 32) {
            int tm = idx >> 3, tn = idx & 7;
            gemm64u(us, ut, barid, 0, g_d1b[(T_STEPS - 1) & 1], 0, 0, H, 0, p.dw2, p.db2, H,
                    g_d2, H, tm * 64, tn * 64, 1, 0);
        }
        gsync(&gen, false);
        if (idx < 16) {
            int tm = idx >> 2, tn = idx & 3;
            gemm64u(us, ut, barid, 0, g_d2, 0, 0, H, 0, p.dlw, p.dlb, OD,
                    p.olog + (size_t)(T_STEPS - 1) * B * OD, OD, tm * 64, tn * 64, 0, 0);
        }
    }
    gsync(&gen, true);
}

extern "C" void kernel_launch(void* const* d_in, const int* in_sizes, int n_in,
                              void* d_out, int out_size) {
    Params p;
    p.x    = (const float*)d_in[0];
    p.eps  = (const float*)d_in[1];
    p.pxw1 = (const float*)d_in[2];  p.pxb1 = (const float*)d_in[3];
    p.pxw2 = (const float*)d_in[4];  p.pxb2 = (const float*)d_in[5];
    p.pzw  = (const float*)d_in[6];  p.pzb  = (const float*)d_in[7];
    p.ew1  = (const float*)d_in[8];  p.eb1  = (const float*)d_in[9];
    p.ew2  = (const float*)d_in[10]; p.eb2  = (const float*)d_in[11];
    p.emw  = (const float*)d_in[12]; p.emb  = (const float*)d_in[13];
    p.esw  = (const float*)d_in[14]; p.esb  = (const float*)d_in[15];
    p.prw  = (const float*)d_in[16]; p.prb  = (const float*)d_in[17];
    p.pmw  = (const float*)d_in[18]; p.pmb  = (const float*)d_in[19];
    p.psw  = (const float*)d_in[20]; p.psb  = (const float*)d_in[21];
    p.dw1  = (const float*)d_in[22]; p.db1  = (const float*)d_in[23];
    p.dw2  = (const float*)d_in[24]; p.db2  = (const float*)d_in[25];
    p.dlw  = (const float*)d_in[26]; p.dlb  = (const float*)d_in[27];
    if (in_sizes[29] == 3 * H) {
        p.gwih = (const float*)d_in[28]; p.gbih = (const float*)d_in[29];
        p.gwhh = (const float*)d_in[30]; p.gbhh = (const float*)d_in[31];
    } else {
        p.gwih = (const float*)d_in[28]; p.gwhh = (const float*)d_in[29];
        p.gbih = (const float*)d_in[30]; p.gbhh = (const float*)d_in[31];
    }

    float* o = (float*)d_out;
    size_t TBZ = (size_t)T_STEPS * B * ZD;
    size_t TBO = (size_t)T_STEPS * B * OD;
    p.oz   = o;
    p.olog = o + TBZ;
    p.oem  = p.olog + TBO;
    p.oes  = p.oem + TBZ;
    p.opm  = p.oes + TBZ;
    p.ops  = p.opm + TBZ;
    p.okld = p.ops + TBZ;

    static bool attr_set = false;
    if (!attr_set) {
        cudaFuncSetAttribute(vrnn_kernel, cudaFuncAttributeMaxDynamicSharedMemorySize, SMEM_BYTES);
        attr_set = true;
    }
    vrnn_kernel<<<NBLK, NTHR, SMEM_BYTES>>>(p);
}